// round 14
// baseline (speedup 1.0000x reference)
#include <cuda_runtime.h>
#include <cuda_fp16.h>
#include <cstdint>

#define N_DIM  2048
#define T_SEQ  8192
#define G_DIM  6144
#define NBLK   128     // persistent blocks (1 per SM, all resident)
#define NTHR   512
#define NWARP  16
#define PB     16      // output elements per block
#define NGATE  3       // z, r, n — each gate = one 16-col A-fragment group
#define KFRAG  8       // k-fragments of 16 per warp (128 k per warp)
#define FRAGS_PER_BLK (NWARP * NGATE * KFRAG * 32 * 4)   // 49152 u32

// ---- scratch (device globals: allocation-free rule) ----
__device__ __half        g_x16[(size_t)T_SEQ * N_DIM];          // 32 MB
__device__ unsigned int  g_whpack[NBLK * FRAGS_PER_BLK];        // 25 MB Wh A-frags
__device__ unsigned int  g_wxpack[NBLK * FRAGS_PER_BLK];        // 25 MB Wx A-frags
__device__ unsigned long long g_hpost[2][NBLK][8];              // 8B packets: {2×fp16, tag}

// ---------------- fused prep: reset + conv_x + pack Wh + pack Wx ----------------
__global__ void prep(const float* __restrict__ x,
                     const float* __restrict__ Wx,
                     const float* __restrict__ Wh) {
    const size_t tg = blockIdx.x * (size_t)blockDim.x + threadIdx.x;
    const size_t nt = (size_t)gridDim.x * blockDim.x;

    // job 0: reset h packets (tag=0 == valid zero h(-1) for step 0)
    for (size_t i = tg; i < 2 * NBLK * 8; i += nt)
        ((unsigned long long*)g_hpost)[i] = 0ull;

    // job 1: x -> fp16
    {
        const float2* x2 = (const float2*)x;
        __half2* o = (__half2*)g_x16;
        const size_t n = (size_t)T_SEQ * N_DIM / 2;
        for (size_t i = tg; i < n; i += nt)
            o[i] = __float22half2_rn(x2[i]);
    }
    // jobs 2+3: pack Wh and Wx into per-block mma A fragments (identical layout)
    for (int m = 0; m < 2; ++m) {
        const float* W = (m == 0) ? Wh : Wx;
        unsigned* dst  = (m == 0) ? g_whpack : g_wxpack;
        const size_t n = (size_t)NBLK * FRAGS_PER_BLK;
        for (size_t ii = tg; ii < n; ii += nt) {
            int idx  = (int)ii;
            int r    = idx & 3;
            int l    = (idx >> 2) & 31;
            int kf   = (idx >> 7) & 7;
            int rest = idx >> 10;          // (b*16 + w)*3 + g
            int g    = rest % 3;
            int bw   = rest / 3;
            int w    = bw & 15;
            int b    = bw >> 4;
            int tid  = l & 3, gid = l >> 2;
            int j    = g * N_DIM + b * PB + gid + ((r & 1) ? 8 : 0);
            int k0   = w * 128 + kf * 16 + ((r & 2) ? 8 : 0) + 2 * tid;
            __half2 h;
            h.x = __float2half(W[(size_t)k0 * G_DIM + j]);
            h.y = __float2half(W[(size_t)(k0 + 1) * G_DIM + j]);
            dst[idx] = *(unsigned int*)&h;
        }
    }
}

// ---------------- persistent GRU scan (fused x@Wx + h@Wh; 8B-atomic tagged dataflow) ----------------
// dynamic smem layout (bytes):
//   [0,196608)        wxp: Wx A-frags for this block (49152 u32)
//   [196608,204800)   red[2][16][64] f32 (parity double-buffered; z,r,hn,xn)
#define SMEM_SCAN 204800

__global__ void __launch_bounds__(NTHR, 1) gru_scan(float* __restrict__ out,
                                                    const float* __restrict__ bias) {
    extern __shared__ unsigned char smem[];
    unsigned int* wxp = (unsigned int*)smem;
    float*        red = (float*)(smem + 196608);

    const int b  = blockIdx.x;
    const int t0 = threadIdx.x;
    const int w  = t0 >> 5, l = t0 & 31, tid = l & 3, gid = l >> 2;
    const int i0 = b * PB;

    // ---- stage this block's Wx fragments into smem (once) ----
    {
        const uint4* src = (const uint4*)(g_wxpack + (size_t)b * FRAGS_PER_BLK);
        uint4* dst = (uint4*)wxp;
        for (int i = t0; i < FRAGS_PER_BLK / 4; i += NTHR) dst[i] = src[i];
    }
    // ---- Wh fragments into registers (persistent, 96 regs) ----
    unsigned breg[NGATE][KFRAG][4];
    {
        const unsigned* base = g_whpack + (size_t)b * FRAGS_PER_BLK;
#pragma unroll
        for (int g = 0; g < NGATE; ++g)
#pragma unroll
            for (int kf = 0; kf < KFRAG; ++kf) {
                const uint4 v = *(const uint4*)(base + (size_t)(((w * NGATE + g) * KFRAG + kf) * 32 + l) * 4);
                breg[g][kf][0] = v.x; breg[g][kf][1] = v.y;
                breg[g][kf][2] = v.z; breg[g][kf][3] = v.w;
            }
    }
    __syncthreads();

    // ---- bias (constant across t): xa low:z high:r ; xb: n ----
    float xa = 0.f, xb = 0.f;
    if (w == 0) {
        if (l < 16) { xa = __ldg(bias + i0 + l); xb = __ldg(bias + 2 * N_DIM + i0 + l); }
        else        { xa = __ldg(bias + N_DIM + i0 + l - 16); }
    }

    const unsigned long long* src0 = &g_hpost[0][w * 8 + (l >> 3)][l & 7];
    const unsigned long long* src1 = &g_hpost[0][w * 8 + ((l + 32) >> 3)][(l + 32) & 7];
    const size_t bufstride = (size_t)NBLK * 8;

    float hprev = 0.f;   // h state, warp 0 lanes 0..15

    for (int t = 0; t < T_SEQ; ++t) {
        // ---- x words for this warp (no recurrence dependence; issued first) ----
        const unsigned* xw = (const unsigned*)g_x16 + (size_t)t * (N_DIM / 2) + w * 64;
        unsigned px0 = __ldg(xw + l);
        unsigned px1 = __ldg(xw + 32 + l);
        if (l < 2 && t + 1 < T_SEQ)
            asm volatile("prefetch.global.L1 [%0];" :: "l"(xw + (N_DIM / 2) + l * 32));

        float acc[NGATE][4];
#pragma unroll
        for (int g = 0; g < NGATE; ++g)
#pragma unroll
            for (int q = 0; q < 4; ++q) acc[g][q] = 0.f;

        // ---- x-mma: A = Wx frags (smem), B = x_t replicated — fills the poll-idle window ----
#pragma unroll
        for (int kf = 0; kf < KFRAG; ++kf) {
            unsigned srcreg = (kf < 4) ? px0 : px1;
            unsigned b0 = __shfl_sync(0xffffffffu, srcreg, (kf * 8 + tid) & 31);
            unsigned b1 = __shfl_sync(0xffffffffu, srcreg, (kf * 8 + 4 + tid) & 31);
#pragma unroll
            for (int g = 0; g < NGATE; ++g) {
                const uint4 av = *(const uint4*)(wxp + (size_t)(((w * NGATE + g) * KFRAG + kf) * 32 + l) * 4);
                asm volatile(
                    "mma.sync.aligned.m16n8k16.row.col.f32.f16.f16.f32 "
                    "{%0,%1,%2,%3},{%4,%5,%6,%7},{%8,%9},{%0,%1,%2,%3};"
                    : "+f"(acc[g][0]), "+f"(acc[g][1]), "+f"(acc[g][2]), "+f"(acc[g][3])
                    : "r"(av.x), "r"(av.y), "r"(av.z), "r"(av.w), "r"(b0), "r"(b1));
            }
        }
        // n-gate x-part must stay separate from h-part (tanh(xn + r*hn))
        float xn0 = acc[2][0], xn2 = acc[2][2];
        acc[2][0] = 0.f; acc[2][1] = 0.f; acc[2][2] = 0.f; acc[2][3] = 0.f;

        // ---- tagged 8B-atomic h acquire into registers ----
        unsigned p0, p1;
        {
            const unsigned long long* s0 = src0 + (t & 1) * bufstride;
            const unsigned long long* s1 = src1 + (t & 1) * bufstride;
            unsigned long long v;
            int got0 = 0, got1 = 0;
            do {
                if (!got0) {
                    asm volatile("ld.global.cg.b64 %0, [%1];" : "=l"(v) : "l"(s0) : "memory");
                    if ((unsigned)(v >> 32) == (unsigned)t) { p0 = (unsigned)v; got0 = 1; }
                }
                if (!got1) {
                    asm volatile("ld.global.cg.b64 %0, [%1];" : "=l"(v) : "l"(s1) : "memory");
                    if ((unsigned)(v >> 32) == (unsigned)t) { p1 = (unsigned)v; got1 = 1; }
                }
            } while (!(got0 & got1));
        }

        // ---- h-mma: A = Wh (regs), B = h replicated via shfl ----
#pragma unroll
        for (int kf = 0; kf < KFRAG; ++kf) {
            unsigned srcreg = (kf < 4) ? p0 : p1;
            unsigned b0 = __shfl_sync(0xffffffffu, srcreg, (kf * 8 + tid) & 31);
            unsigned b1 = __shfl_sync(0xffffffffu, srcreg, (kf * 8 + 4 + tid) & 31);
#pragma unroll
            for (int g = 0; g < NGATE; ++g) {
                asm volatile(
                    "mma.sync.aligned.m16n8k16.row.col.f32.f16.f16.f32 "
                    "{%0,%1,%2,%3},{%4,%5,%6,%7},{%8,%9},{%0,%1,%2,%3};"
                    : "+f"(acc[g][0]), "+f"(acc[g][1]), "+f"(acc[g][2]), "+f"(acc[g][3])
                    : "r"(breg[g][kf][0]), "r"(breg[g][kf][1]),
                      "r"(breg[g][kf][2]), "r"(breg[g][kf][3]),
                      "r"(b0), "r"(b1));
            }
        }
        // ---- partials (parity double-buffered): z | r | hn | xn ----
        float* redp = red + (t & 1) * 1024;
        if (tid == 0) {
            redp[w * 64 + gid]           = acc[0][0];
            redp[w * 64 + gid + 8]       = acc[0][2];
            redp[w * 64 + 16 + gid]      = acc[1][0];
            redp[w * 64 + 16 + gid + 8]  = acc[1][2];
            redp[w * 64 + 32 + gid]      = acc[2][0];
            redp[w * 64 + 32 + gid + 8]  = acc[2][2];
            redp[w * 64 + 48 + gid]      = xn0;
            redp[w * 64 + 48 + gid + 8]  = xn2;
        }
        __syncthreads();   // B2: the only block barrier

        // ---- reduce + activation + register-packed publish (warp 0 only) ----
        if (w == 0) {
            float sa = 0.f, sb = 0.f, sx = 0.f;
#pragma unroll
            for (int ww = 0; ww < NWARP; ++ww) {
                sa += redp[ww * 64 + l];                       // l<16: z, l>=16: r
                sb += redp[ww * 64 + 32 + (l & 15)];           // hn
                sx += redp[ww * 64 + 48 + (l & 15)];           // xn
            }
            float sig = __fdividef(1.f, 1.f + __expf(-(xa + sa)));  // low: z, high: r
            float r   = __shfl_sync(0xffffffffu, sig, (l + 16) & 31);
            float ci  = xb + sx + r * sb;
            ci = fminf(fmaxf(ci, -15.f), 15.f);
            float e2  = __expf(2.f * ci);
            float cand = __fdividef(e2 - 1.f, e2 + 1.f);
            float hn = fmaf(sig, cand - hprev, hprev);        // valid in lanes 0..15
            if (l < 16) {
                hprev = hn;
                out[(size_t)t * N_DIM + i0 + l] = hn;
            }
            unsigned us = (unsigned)__half_as_ushort(__float2half(hn));
            unsigned lo = __shfl_sync(0xffffffffu, us, (2 * l) & 31);
            unsigned hi = __shfl_sync(0xffffffffu, us, (2 * l + 1) & 31);
            unsigned wreg = (hi << 16) | (lo & 0xffffu);
            if (l < 8) {
                unsigned long long pkt = (unsigned long long)wreg
                                       | ((unsigned long long)(unsigned)(t + 1) << 32);
                unsigned long long* dst = &g_hpost[(t + 1) & 1][b][l];
                asm volatile("st.global.cg.b64 [%0], %1;" :: "l"(dst), "l"(pkt) : "memory");
            }
        }
    }
}

// ---------------- launcher ----------------
extern "C" void kernel_launch(void* const* d_in, const int* in_sizes, int n_in,
                              void* d_out, int out_size) {
    const float* x    = (const float*)d_in[0];
    const float* Wx   = (const float*)d_in[1];
    const float* Wh   = (const float*)d_in[2];
    const float* bias = (const float*)d_in[3];
    float* out = (float*)d_out;

    cudaFuncSetAttribute(gru_scan, cudaFuncAttributeMaxDynamicSharedMemorySize, SMEM_SCAN);

    prep<<<4096, 256>>>(x, Wx, Wh);
    gru_scan<<<NBLK, NTHR, SMEM_SCAN>>>(out, bias);
}

// round 15
// speedup vs baseline: 1.6046x; 1.6046x over previous
#include <cuda_runtime.h>
#include <cuda_fp16.h>
#include <cstdint>

#define N_DIM  2048
#define T_SEQ  8192
#define G_DIM  6144
#define NBLK   128     // persistent blocks (1 per SM, all resident)
#define NTHR   512
#define NWARP  16
#define PB     16      // output elements per block
#define NGATE  3       // z, r, n — each gate = one 16-col A-fragment group
#define KFRAG  8       // k-fragments of 16 per warp (128 k per warp)

// ---- scratch (device globals: allocation-free rule) ----
__device__ __half        g_x16[(size_t)T_SEQ * N_DIM];          // 32 MB
__device__ __half        g_WxT16[(size_t)G_DIM * N_DIM];        // 25 MB (transposed: [n][k])
__device__ float         g_gx[(size_t)T_SEQ * G_DIM];           // 192 MB
__device__ unsigned int  g_whpack[NBLK * NWARP * NGATE * KFRAG * 32 * 4]; // 25 MB packed A-frags
__device__ unsigned long long g_hpost[2][NBLK][8];              // 8B packets: {2×fp16, tag}

// ---------------- fused prep: reset + conv_x + tiled WxT transpose + pack_wh ----------------
__global__ void prep(const float* __restrict__ x,
                     const float* __restrict__ Wx,
                     const float* __restrict__ Wh) {
    __shared__ __half tile[32][72];   // 32 k-rows x 64 j-cols, padded
    const size_t tg = blockIdx.x * (size_t)blockDim.x + threadIdx.x;
    const size_t nt = (size_t)gridDim.x * blockDim.x;
    const int    tl = threadIdx.x;

    // job 0: reset h packets (tag=0 == valid zero h(-1) for step 0)
    for (size_t i = tg; i < 2 * NBLK * 8; i += nt)
        ((unsigned long long*)g_hpost)[i] = 0ull;

    // job 1: x -> fp16
    {
        const float2* x2 = (const float2*)x;
        __half2* o = (__half2*)g_x16;
        const size_t n = (size_t)T_SEQ * N_DIM / 2;
        for (size_t i = tg; i < n; i += nt)
            o[i] = __float22half2_rn(x2[i]);
    }
    // job 3: Wh -> packed A-fragments
    {
        const size_t n = (size_t)NBLK * NWARP * NGATE * KFRAG * 32 * 4;
        for (size_t ii = tg; ii < n; ii += nt) {
            int idx  = (int)ii;
            int r    = idx & 3;
            int l    = (idx >> 2) & 31;
            int kf   = (idx >> 7) & 7;
            int rest = idx >> 10;          // (b*16 + w)*3 + g
            int g    = rest % 3;
            int bw   = rest / 3;
            int w    = bw & 15;
            int b    = bw >> 4;
            int tid  = l & 3, gid = l >> 2;
            int j    = g * N_DIM + b * PB + gid + ((r & 1) ? 8 : 0);
            int k0   = w * 128 + kf * 16 + ((r & 2) ? 8 : 0) + 2 * tid;
            __half2 h;
            h.x = __float2half(Wh[(size_t)k0 * G_DIM + j]);
            h.y = __float2half(Wh[(size_t)(k0 + 1) * G_DIM + j]);
            g_whpack[idx] = *(unsigned int*)&h;
        }
    }
    // job 2 (last; block-uniform): Wx -> WxT fp16 [n][k], tiled smem transpose
    {
        const int ntile = (N_DIM / 32) * (G_DIM / 64);   // 64 * 96 = 6144
        for (int tix = blockIdx.x; tix < ntile; tix += gridDim.x) {
            int tk = tix & 63, tj = tix >> 6;
            int k0 = tk * 32, j0 = tj * 64;
            __syncthreads();
#pragma unroll
            for (int e = 0; e < 8; ++e) {
                int idx = tl + e * 256;         // 0..2047
                int kk = idx >> 6, jj = idx & 63;
                tile[kk][jj] = __float2half(Wx[(size_t)(k0 + kk) * G_DIM + j0 + jj]);
            }
            __syncthreads();
#pragma unroll
            for (int e = 0; e < 8; ++e) {
                int idx = tl + e * 256;
                int jj = idx >> 5, kk = idx & 31;
                g_WxT16[(size_t)(j0 + jj) * N_DIM + k0 + kk] = tile[kk][jj];
            }
        }
    }
}

// ---------------- gx = x @ Wx + b  (fp16 mma, fp32 accum, 2-stage cp.async) ----------------
#define CP_ASYNC16(sa, gp) \
    asm volatile("cp.async.ca.shared.global [%0], [%1], 16;" :: "r"(sa), "l"(gp))
#define CP_COMMIT() asm volatile("cp.async.commit_group;" ::: "memory")

__global__ void __launch_bounds__(256) gemm_gx(const float* __restrict__ bias) {
    __shared__ __half As[2][128 * 40];
    __shared__ __half Bs[2][128 * 40];
    const int m0 = blockIdx.y * 128, n0 = blockIdx.x * 128;
    const int t = threadIdx.x, w = t >> 5, l = t & 31, tid = l & 3, gid = l >> 2;
    const int wm = w & 3, wn = w >> 2;
    const int r = t >> 2, c = (t & 3) * 8;

    float acc[2][8][4];
#pragma unroll
    for (int mt = 0; mt < 2; ++mt)
#pragma unroll
        for (int nt = 0; nt < 8; ++nt)
#pragma unroll
            for (int q = 0; q < 4; ++q) acc[mt][nt][q] = 0.f;

    auto load_stage = [&](int s, int kt) {
        unsigned a0 = (unsigned)__cvta_generic_to_shared(&As[s][r * 40 + c]);
        unsigned a1 = (unsigned)__cvta_generic_to_shared(&As[s][(r + 64) * 40 + c]);
        unsigned b0 = (unsigned)__cvta_generic_to_shared(&Bs[s][r * 40 + c]);
        unsigned b1 = (unsigned)__cvta_generic_to_shared(&Bs[s][(r + 64) * 40 + c]);
        CP_ASYNC16(a0, g_x16  + (size_t)(m0 + r)      * N_DIM + kt + c);
        CP_ASYNC16(a1, g_x16  + (size_t)(m0 + r + 64) * N_DIM + kt + c);
        CP_ASYNC16(b0, g_WxT16 + (size_t)(n0 + r)      * N_DIM + kt + c);
        CP_ASYNC16(b1, g_WxT16 + (size_t)(n0 + r + 64) * N_DIM + kt + c);
        CP_COMMIT();
    };

    load_stage(0, 0);
    const int NIT = N_DIM / 32;
    for (int i = 0; i < NIT; ++i) {
        const int s = i & 1;
        if (i + 1 < NIT) {
            load_stage(s ^ 1, (i + 1) * 32);
            asm volatile("cp.async.wait_group 1;" ::: "memory");
        } else {
            asm volatile("cp.async.wait_group 0;" ::: "memory");
        }
        __syncthreads();
#pragma unroll
        for (int sj = 0; sj < 2; ++sj) {
            const int ko = sj * 16;
            unsigned a[2][4];
#pragma unroll
            for (int mt = 0; mt < 2; ++mt) {
                int rb = wm * 32 + mt * 16;
                a[mt][0] = *(const unsigned*)(&As[s][(rb + gid)     * 40 + ko + 2 * tid]);
                a[mt][1] = *(const unsigned*)(&As[s][(rb + gid + 8) * 40 + ko + 2 * tid]);
                a[mt][2] = *(const unsigned*)(&As[s][(rb + gid)     * 40 + ko + 2 * tid + 8]);
                a[mt][3] = *(const unsigned*)(&As[s][(rb + gid + 8) * 40 + ko + 2 * tid + 8]);
            }
#pragma unroll
            for (int nt = 0; nt < 8; ++nt) {
                int cb = wn * 64 + nt * 8 + gid;
                unsigned b0 = *(const unsigned*)(&Bs[s][cb * 40 + ko + 2 * tid]);
                unsigned b1 = *(const unsigned*)(&Bs[s][cb * 40 + ko + 2 * tid + 8]);
#pragma unroll
                for (int mt = 0; mt < 2; ++mt) {
                    asm volatile(
                        "mma.sync.aligned.m16n8k16.row.col.f32.f16.f16.f32 "
                        "{%0,%1,%2,%3},{%4,%5,%6,%7},{%8,%9},{%0,%1,%2,%3};"
                        : "+f"(acc[mt][nt][0]), "+f"(acc[mt][nt][1]),
                          "+f"(acc[mt][nt][2]), "+f"(acc[mt][nt][3])
                        : "r"(a[mt][0]), "r"(a[mt][1]), "r"(a[mt][2]), "r"(a[mt][3]),
                          "r"(b0), "r"(b1));
                }
            }
        }
        __syncthreads();
    }
#pragma unroll
    for (int mt = 0; mt < 2; ++mt)
#pragma unroll
        for (int nt = 0; nt < 8; ++nt) {
            int row = m0 + wm * 32 + mt * 16 + gid;
            int col = n0 + wn * 64 + nt * 8 + 2 * tid;
            float b0v = __ldg(bias + col), b1v = __ldg(bias + col + 1);
            g_gx[(size_t)row * G_DIM + col]           = acc[mt][nt][0] + b0v;
            g_gx[(size_t)row * G_DIM + col + 1]       = acc[mt][nt][1] + b1v;
            g_gx[(size_t)(row + 8) * G_DIM + col]     = acc[mt][nt][2] + b0v;
            g_gx[(size_t)(row + 8) * G_DIM + col + 1] = acc[mt][nt][3] + b1v;
        }
}

// ---------------- persistent GRU scan (8B-atomic tagged dataflow; register B-path) ----------------
// dynamic smem layout (bytes):
//   [0,6144)  red[2][16][48] f32 (parity double-buffered)
#define SMEM_SCAN 6144

__global__ void __launch_bounds__(NTHR, 1) gru_scan(float* __restrict__ out) {
    extern __shared__ unsigned char smem[];
    float* red = (float*)smem;

    const int b  = blockIdx.x;
    const int t0 = threadIdx.x;
    const int w  = t0 >> 5, l = t0 & 31, tid = l & 3, gid = l >> 2;
    const int i0 = b * PB;

    const unsigned* base = g_whpack + (size_t)b * 49152;

    unsigned breg[NGATE][KFRAG][4];
#pragma unroll
    for (int g = 0; g < NGATE; ++g)
#pragma unroll
        for (int kf = 0; kf < KFRAG; ++kf) {
            const uint4 v = *(const uint4*)(base + (size_t)(((w * NGATE + g) * KFRAG + kf) * 32 + l) * 4);
            breg[g][kf][0] = v.x; breg[g][kf][1] = v.y;
            breg[g][kf][2] = v.z; breg[g][kf][3] = v.w;
        }
    __syncthreads();

    if (w == 0 && l < 3) {
        const float* p = g_gx + (size_t)l * N_DIM + i0;
        asm volatile("prefetch.global.L1 [%0];" :: "l"(p));
    }

    const unsigned long long* src0 = &g_hpost[0][w * 8 + (l >> 3)][l & 7];
    const unsigned long long* src1 = &g_hpost[0][w * 8 + ((l + 32) >> 3)][(l + 32) & 7];
    const size_t bufstride = (size_t)NBLK * 8;

    float hprev = 0.f;

    for (int t = 0; t < T_SEQ; ++t) {
        if (w == 0 && l < 3 && t + 1 < T_SEQ) {
            const float* p = g_gx + (size_t)(t + 1) * G_DIM + (size_t)l * N_DIM + i0;
            asm volatile("prefetch.global.L1 [%0];" :: "l"(p));
        }
        float xa = 0.f, xb = 0.f;
        if (w == 0) {
            const float* gxr = g_gx + (size_t)t * G_DIM + i0;
            if (l < 16) { xa = __ldg(gxr + l); xb = __ldg(gxr + 2 * N_DIM + l); }
            else        { xa = __ldg(gxr + N_DIM + l - 16); }
        }

        unsigned p0, p1;
        {
            const unsigned long long* s0 = src0 + (t & 1) * bufstride;
            const unsigned long long* s1 = src1 + (t & 1) * bufstride;
            unsigned long long v;
            int got0 = 0, got1 = 0;
            do {
                if (!got0) {
                    asm volatile("ld.global.cg.b64 %0, [%1];" : "=l"(v) : "l"(s0) : "memory");
                    if ((unsigned)(v >> 32) == (unsigned)t) { p0 = (unsigned)v; got0 = 1; }
                }
                if (!got1) {
                    asm volatile("ld.global.cg.b64 %0, [%1];" : "=l"(v) : "l"(s1) : "memory");
                    if ((unsigned)(v >> 32) == (unsigned)t) { p1 = (unsigned)v; got1 = 1; }
                }
            } while (!(got0 & got1));
        }

        float acc[NGATE][4];
#pragma unroll
        for (int g = 0; g < NGATE; ++g)
#pragma unroll
            for (int q = 0; q < 4; ++q) acc[g][q] = 0.f;

#pragma unroll
        for (int kf = 0; kf < KFRAG; ++kf) {
            unsigned srcreg = (kf < 4) ? p0 : p1;
            unsigned b0 = __shfl_sync(0xffffffffu, srcreg, (kf * 8 + tid) & 31);
            unsigned b1 = __shfl_sync(0xffffffffu, srcreg, (kf * 8 + 4 + tid) & 31);
#pragma unroll
            for (int g = 0; g < NGATE; ++g) {
                asm volatile(
                    "mma.sync.aligned.m16n8k16.row.col.f32.f16.f16.f32 "
                    "{%0,%1,%2,%3},{%4,%5,%6,%7},{%8,%9},{%0,%1,%2,%3};"
                    : "+f"(acc[g][0]), "+f"(acc[g][1]), "+f"(acc[g][2]), "+f"(acc[g][3])
                    : "r"(breg[g][kf][0]), "r"(breg[g][kf][1]),
                      "r"(breg[g][kf][2]), "r"(breg[g][kf][3]),
                      "r"(b0), "r"(b1));
            }
        }
        float* redp = red + (t & 1) * 768;
        if (tid == 0) {
#pragma unroll
            for (int g = 0; g < NGATE; ++g) {
                redp[w * 48 + g * 16 + gid]     = acc[g][0];
                redp[w * 48 + g * 16 + gid + 8] = acc[g][2];
            }
        }
        __syncthreads();

        if (w == 0) {
            // balanced reduce: sa full per lane; n-partials split across half-warps, shfl-combined
            float sa = 0.f, sbh = 0.f;
            const int wo = (l >= 16) ? 8 : 0;
#pragma unroll
            for (int ww = 0; ww < NWARP; ++ww) sa += redp[ww * 48 + l];
#pragma unroll
            for (int ww = 0; ww < 8; ++ww) sbh += redp[(ww + wo) * 48 + 32 + (l & 15)];
            float sb = sbh + __shfl_sync(0xffffffffu, sbh, (l + 16) & 31);
            float sig = __fdividef(1.f, 1.f + __expf(-(xa + sa)));
            float r   = __shfl_sync(0xffffffffu, sig, (l + 16) & 31);
            float ci  = xb + r * sb;
            ci = fminf(fmaxf(ci, -15.f), 15.f);
            float e2  = __expf(2.f * ci);
            float cand = __fdividef(e2 - 1.f, e2 + 1.f);
            float hn = fmaf(sig, cand - hprev, hprev);
            if (l < 16) {
                hprev = hn;
                out[(size_t)t * N_DIM + i0 + l] = hn;
            }
            unsigned us = (unsigned)__half_as_ushort(__float2half(hn));
            unsigned lo = __shfl_sync(0xffffffffu, us, (2 * l) & 31);
            unsigned hi = __shfl_sync(0xffffffffu, us, (2 * l + 1) & 31);
            unsigned wreg = (hi << 16) | (lo & 0xffffu);
            if (l < 8) {
                unsigned long long pkt = (unsigned long long)wreg
                                       | ((unsigned long long)(unsigned)(t + 1) << 32);
                unsigned long long* dst = &g_hpost[(t + 1) & 1][b][l];
                asm volatile("st.global.cg.b64 [%0], %1;" :: "l"(dst), "l"(pkt) : "memory");
            }
        }
    }
}

// ---------------- launcher ----------------
extern "C" void kernel_launch(void* const* d_in, const int* in_sizes, int n_in,
                              void* d_out, int out_size) {
    const float* x    = (const float*)d_in[0];
    const float* Wx   = (const float*)d_in[1];
    const float* Wh   = (const float*)d_in[2];
    const float* bias = (const float*)d_in[3];
    float* out = (float*)d_out;

    cudaFuncSetAttribute(gru_scan, cudaFuncAttributeMaxDynamicSharedMemorySize, SMEM_SCAN);

    prep<<<4096, 256>>>(x, Wx, Wh);
    gemm_gx<<<dim3(G_DIM / 128, T_SEQ / 128), 256>>>(bias);
    gru_scan<<<NBLK, NTHR, SMEM_SCAN>>>(out);
}

// round 16
// speedup vs baseline: 1.6056x; 1.0006x over previous
#include <cuda_runtime.h>
#include <cuda_fp16.h>
#include <cstdint>

#define N_DIM  2048
#define T_SEQ  8192
#define G_DIM  6144
#define NBLK   128     // persistent blocks (1 per SM, all resident)
#define NTHR   512
#define NWARP  16
#define PB     16      // output elements per block
#define NGATE  3       // z, r, n — each gate = one 16-col A-fragment group
#define KFRAG  8       // k-fragments of 16 per warp (128 k per warp)

// ---- scratch (device globals: allocation-free rule) ----
__device__ __half        g_x16[(size_t)T_SEQ * N_DIM];          // 32 MB
__device__ __half        g_WxT16[(size_t)G_DIM * N_DIM];        // 25 MB (transposed: [n][k])
__device__ float         g_gx[(size_t)T_SEQ * G_DIM];           // 192 MB
__device__ unsigned int  g_whpack[NBLK * NWARP * NGATE * KFRAG * 32 * 4]; // 25 MB packed A-frags
__device__ unsigned long long g_hpost[2][NBLK][8];              // 8B packets: {2×fp16, tag}

// ---------------- fused prep: reset + conv_x + tiled WxT transpose + pack_wh ----------------
__global__ void prep(const float* __restrict__ x,
                     const float* __restrict__ Wx,
                     const float* __restrict__ Wh) {
    __shared__ __half tile[32][72];   // 32 k-rows x 64 j-cols, padded
    const size_t tg = blockIdx.x * (size_t)blockDim.x + threadIdx.x;
    const size_t nt = (size_t)gridDim.x * blockDim.x;
    const int    tl = threadIdx.x;

    // job 0: reset h packets (tag=0 == valid zero h(-1) for step 0)
    for (size_t i = tg; i < 2 * NBLK * 8; i += nt)
        ((unsigned long long*)g_hpost)[i] = 0ull;

    // job 1: x -> fp16
    {
        const float2* x2 = (const float2*)x;
        __half2* o = (__half2*)g_x16;
        const size_t n = (size_t)T_SEQ * N_DIM / 2;
        for (size_t i = tg; i < n; i += nt)
            o[i] = __float22half2_rn(x2[i]);
    }
    // job 3: Wh -> packed A-fragments
    {
        const size_t n = (size_t)NBLK * NWARP * NGATE * KFRAG * 32 * 4;
        for (size_t ii = tg; ii < n; ii += nt) {
            int idx  = (int)ii;
            int r    = idx & 3;
            int l    = (idx >> 2) & 31;
            int kf   = (idx >> 7) & 7;
            int rest = idx >> 10;          // (b*16 + w)*3 + g
            int g    = rest % 3;
            int bw   = rest / 3;
            int w    = bw & 15;
            int b    = bw >> 4;
            int tid  = l & 3, gid = l >> 2;
            int j    = g * N_DIM + b * PB + gid + ((r & 1) ? 8 : 0);
            int k0   = w * 128 + kf * 16 + ((r & 2) ? 8 : 0) + 2 * tid;
            __half2 h;
            h.x = __float2half(Wh[(size_t)k0 * G_DIM + j]);
            h.y = __float2half(Wh[(size_t)(k0 + 1) * G_DIM + j]);
            g_whpack[idx] = *(unsigned int*)&h;
        }
    }
    // job 2 (last; block-uniform): Wx -> WxT fp16 [n][k], tiled smem transpose
    {
        const int ntile = (N_DIM / 32) * (G_DIM / 64);   // 64 * 96 = 6144
        for (int tix = blockIdx.x; tix < ntile; tix += gridDim.x) {
            int tk = tix & 63, tj = tix >> 6;
            int k0 = tk * 32, j0 = tj * 64;
            __syncthreads();
#pragma unroll
            for (int e = 0; e < 8; ++e) {
                int idx = tl + e * 256;         // 0..2047
                int kk = idx >> 6, jj = idx & 63;
                tile[kk][jj] = __float2half(Wx[(size_t)(k0 + kk) * G_DIM + j0 + jj]);
            }
            __syncthreads();
#pragma unroll
            for (int e = 0; e < 8; ++e) {
                int idx = tl + e * 256;
                int jj = idx >> 5, kk = idx & 31;
                g_WxT16[(size_t)(j0 + jj) * N_DIM + k0 + kk] = tile[kk][jj];
            }
        }
    }
}

// ---------------- gx = x @ Wx + b  (fp16 mma, fp32 accum, BK=64, 2-stage cp.async) ----------------
#define CP_ASYNC16(sa, gp) \
    asm volatile("cp.async.ca.shared.global [%0], [%1], 16;" :: "r"(sa), "l"(gp))
#define CP_COMMIT() asm volatile("cp.async.commit_group;" ::: "memory")
#define SROW 72                       // padded row width (halfs) for 64-wide k-chunk
#define SST  (128 * SROW)             // halfs per stage per matrix
#define GEMM_SMEM (4 * SST * 2)       // bytes: 2 matrices x 2 stages

__global__ void __launch_bounds__(256) gemm_gx(const float* __restrict__ bias) {
    extern __shared__ __half gsm[];
    __half* Asm = gsm;                // [2][SST]
    __half* Bsm = gsm + 2 * SST;      // [2][SST]
    const int m0 = blockIdx.y * 128, n0 = blockIdx.x * 128;
    const int t = threadIdx.x, w = t >> 5, l = t & 31, tid = l & 3, gid = l >> 2;
    const int wm = w & 3, wn = w >> 2;

    float acc[2][8][4];
#pragma unroll
    for (int mt = 0; mt < 2; ++mt)
#pragma unroll
        for (int nt = 0; nt < 8; ++nt)
#pragma unroll
            for (int q = 0; q < 4; ++q) acc[mt][nt][q] = 0.f;

    auto load_stage = [&](int s, int kt) {
#pragma unroll
        for (int e = 0; e < 4; ++e) {
            int id = t + e * 256;        // 0..1023 : 128 rows x 8 16B-chunks
            int row = id >> 3, c16 = (id & 7) * 8;
            unsigned da = (unsigned)__cvta_generic_to_shared(Asm + s * SST + row * SROW + c16);
            unsigned db = (unsigned)__cvta_generic_to_shared(Bsm + s * SST + row * SROW + c16);
            CP_ASYNC16(da, g_x16   + (size_t)(m0 + row) * N_DIM + kt + c16);
            CP_ASYNC16(db, g_WxT16 + (size_t)(n0 + row) * N_DIM + kt + c16);
        }
        CP_COMMIT();
    };

    load_stage(0, 0);
    const int NIT = N_DIM / 64;
    for (int i = 0; i < NIT; ++i) {
        const int s = i & 1;
        if (i + 1 < NIT) {
            load_stage(s ^ 1, (i + 1) * 64);
            asm volatile("cp.async.wait_group 1;" ::: "memory");
        } else {
            asm volatile("cp.async.wait_group 0;" ::: "memory");
        }
        __syncthreads();
        const __half* As = Asm + s * SST;
        const __half* Bs = Bsm + s * SST;
#pragma unroll
        for (int sj = 0; sj < 4; ++sj) {
            const int ko = sj * 16;
            unsigned a[2][4];
#pragma unroll
            for (int mt = 0; mt < 2; ++mt) {
                int rb = wm * 32 + mt * 16;
                a[mt][0] = *(const unsigned*)(&As[(rb + gid)     * SROW + ko + 2 * tid]);
                a[mt][1] = *(const unsigned*)(&As[(rb + gid + 8) * SROW + ko + 2 * tid]);
                a[mt][2] = *(const unsigned*)(&As[(rb + gid)     * SROW + ko + 2 * tid + 8]);
                a[mt][3] = *(const unsigned*)(&As[(rb + gid + 8) * SROW + ko + 2 * tid + 8]);
            }
#pragma unroll
            for (int nt = 0; nt < 8; ++nt) {
                int cb = wn * 64 + nt * 8 + gid;
                unsigned b0 = *(const unsigned*)(&Bs[cb * SROW + ko + 2 * tid]);
                unsigned b1 = *(const unsigned*)(&Bs[cb * SROW + ko + 2 * tid + 8]);
#pragma unroll
                for (int mt = 0; mt < 2; ++mt) {
                    asm volatile(
                        "mma.sync.aligned.m16n8k16.row.col.f32.f16.f16.f32 "
                        "{%0,%1,%2,%3},{%4,%5,%6,%7},{%8,%9},{%0,%1,%2,%3};"
                        : "+f"(acc[mt][nt][0]), "+f"(acc[mt][nt][1]),
                          "+f"(acc[mt][nt][2]), "+f"(acc[mt][nt][3])
                        : "r"(a[mt][0]), "r"(a[mt][1]), "r"(a[mt][2]), "r"(a[mt][3]),
                          "r"(b0), "r"(b1));
                }
            }
        }
        __syncthreads();
    }
#pragma unroll
    for (int mt = 0; mt < 2; ++mt)
#pragma unroll
        for (int nt = 0; nt < 8; ++nt) {
            int row = m0 + wm * 32 + mt * 16 + gid;
            int col = n0 + wn * 64 + nt * 8 + 2 * tid;
            float b0v = __ldg(bias + col), b1v = __ldg(bias + col + 1);
            g_gx[(size_t)row * G_DIM + col]           = acc[mt][nt][0] + b0v;
            g_gx[(size_t)row * G_DIM + col + 1]       = acc[mt][nt][1] + b1v;
            g_gx[(size_t)(row + 8) * G_DIM + col]     = acc[mt][nt][2] + b0v;
            g_gx[(size_t)(row + 8) * G_DIM + col + 1] = acc[mt][nt][3] + b1v;
        }
}

// ---------------- persistent GRU scan (R13 byte-exact; 8B-atomic tagged dataflow) ----------------
// dynamic smem layout (bytes):
//   [0,6144)  red[2][16][48] f32 (parity double-buffered)
#define SMEM_SCAN 6144

__global__ void __launch_bounds__(NTHR, 1) gru_scan(float* __restrict__ out) {
    extern __shared__ unsigned char smem[];
    float* red = (float*)smem;

    const int b  = blockIdx.x;
    const int t0 = threadIdx.x;
    const int w  = t0 >> 5, l = t0 & 31, tid = l & 3, gid = l >> 2;
    const int i0 = b * PB;

    const unsigned* base = g_whpack + (size_t)b * 49152;

    unsigned breg[NGATE][KFRAG][4];
#pragma unroll
    for (int g = 0; g < NGATE; ++g)
#pragma unroll
        for (int kf = 0; kf < KFRAG; ++kf) {
            const uint4 v = *(const uint4*)(base + (size_t)(((w * NGATE + g) * KFRAG + kf) * 32 + l) * 4);
            breg[g][kf][0] = v.x; breg[g][kf][1] = v.y;
            breg[g][kf][2] = v.z; breg[g][kf][3] = v.w;
        }
    __syncthreads();

    if (w == 0 && l < 3) {
        const float* p = g_gx + (size_t)l * N_DIM + i0;
        asm volatile("prefetch.global.L1 [%0];" :: "l"(p));
    }

    const unsigned long long* src0 = &g_hpost[0][w * 8 + (l >> 3)][l & 7];
    const unsigned long long* src1 = &g_hpost[0][w * 8 + ((l + 32) >> 3)][(l + 32) & 7];
    const size_t bufstride = (size_t)NBLK * 8;

    float hprev = 0.f;

    for (int t = 0; t < T_SEQ; ++t) {
        if (w == 0 && l < 3 && t + 1 < T_SEQ) {
            const float* p = g_gx + (size_t)(t + 1) * G_DIM + (size_t)l * N_DIM + i0;
            asm volatile("prefetch.global.L1 [%0];" :: "l"(p));
        }
        float xa = 0.f, xb = 0.f;
        if (w == 0) {
            const float* gxr = g_gx + (size_t)t * G_DIM + i0;
            if (l < 16) { xa = __ldg(gxr + l); xb = __ldg(gxr + 2 * N_DIM + l); }
            else        { xa = __ldg(gxr + N_DIM + l - 16); }
        }

        unsigned p0, p1;
        {
            const unsigned long long* s0 = src0 + (t & 1) * bufstride;
            const unsigned long long* s1 = src1 + (t & 1) * bufstride;
            unsigned long long v;
            int got0 = 0, got1 = 0;
            do {
                if (!got0) {
                    asm volatile("ld.global.cg.b64 %0, [%1];" : "=l"(v) : "l"(s0) : "memory");
                    if ((unsigned)(v >> 32) == (unsigned)t) { p0 = (unsigned)v; got0 = 1; }
                }
                if (!got1) {
                    asm volatile("ld.global.cg.b64 %0, [%1];" : "=l"(v) : "l"(s1) : "memory");
                    if ((unsigned)(v >> 32) == (unsigned)t) { p1 = (unsigned)v; got1 = 1; }
                }
            } while (!(got0 & got1));
        }

        float acc[NGATE][4];
#pragma unroll
        for (int g = 0; g < NGATE; ++g)
#pragma unroll
            for (int q = 0; q < 4; ++q) acc[g][q] = 0.f;

#pragma unroll
        for (int kf = 0; kf < KFRAG; ++kf) {
            unsigned srcreg = (kf < 4) ? p0 : p1;
            unsigned b0 = __shfl_sync(0xffffffffu, srcreg, (kf * 8 + tid) & 31);
            unsigned b1 = __shfl_sync(0xffffffffu, srcreg, (kf * 8 + 4 + tid) & 31);
#pragma unroll
            for (int g = 0; g < NGATE; ++g) {
                asm volatile(
                    "mma.sync.aligned.m16n8k16.row.col.f32.f16.f16.f32 "
                    "{%0,%1,%2,%3},{%4,%5,%6,%7},{%8,%9},{%0,%1,%2,%3};"
                    : "+f"(acc[g][0]), "+f"(acc[g][1]), "+f"(acc[g][2]), "+f"(acc[g][3])
                    : "r"(breg[g][kf][0]), "r"(breg[g][kf][1]),
                      "r"(breg[g][kf][2]), "r"(breg[g][kf][3]),
                      "r"(b0), "r"(b1));
            }
        }
        float* redp = red + (t & 1) * 768;
        if (tid == 0) {
#pragma unroll
            for (int g = 0; g < NGATE; ++g) {
                redp[w * 48 + g * 16 + gid]     = acc[g][0];
                redp[w * 48 + g * 16 + gid + 8] = acc[g][2];
            }
        }
        __syncthreads();

        if (w == 0) {
            float sa = 0.f, sb = 0.f;
#pragma unroll
            for (int ww = 0; ww < NWARP; ++ww) {
                sa += redp[ww * 48 + l];
                sb += redp[ww * 48 + 32 + (l & 15)];
            }
            float sig = __fdividef(1.f, 1.f + __expf(-(xa + sa)));
            float r   = __shfl_sync(0xffffffffu, sig, (l + 16) & 31);
            float ci  = xb + r * sb;
            ci = fminf(fmaxf(ci, -15.f), 15.f);
            float e2  = __expf(2.f * ci);
            float cand = __fdividef(e2 - 1.f, e2 + 1.f);
            float hn = fmaf(sig, cand - hprev, hprev);
            if (l < 16) {
                hprev = hn;
                out[(size_t)t * N_DIM + i0 + l] = hn;
            }
            unsigned us = (unsigned)__half_as_ushort(__float2half(hn));
            unsigned lo = __shfl_sync(0xffffffffu, us, (2 * l) & 31);
            unsigned hi = __shfl_sync(0xffffffffu, us, (2 * l + 1) & 31);
            unsigned wreg = (hi << 16) | (lo & 0xffffu);
            if (l < 8) {
                unsigned long long pkt = (unsigned long long)wreg
                                       | ((unsigned long long)(unsigned)(t + 1) << 32);
                unsigned long long* dst = &g_hpost[(t + 1) & 1][b][l];
                asm volatile("st.global.cg.b64 [%0], %1;" :: "l"(dst), "l"(pkt) : "memory");
            }
        }
    }
}

// ---------------- launcher ----------------
extern "C" void kernel_launch(void* const* d_in, const int* in_sizes, int n_in,
                              void* d_out, int out_size) {
    const float* x    = (const float*)d_in[0];
    const float* Wx   = (const float*)d_in[1];
    const float* Wh   = (const float*)d_in[2];
    const float* bias = (const float*)d_in[3];
    float* out = (float*)d_out;

    cudaFuncSetAttribute(gru_scan, cudaFuncAttributeMaxDynamicSharedMemorySize, SMEM_SCAN);
    cudaFuncSetAttribute(gemm_gx, cudaFuncAttributeMaxDynamicSharedMemorySize, GEMM_SMEM);

    prep<<<4096, 256>>>(x, Wx, Wh);
    gemm_gx<<<dim3(G_DIM / 128, T_SEQ / 128), 256, GEMM_SMEM>>>(bias);
    gru_scan<<<NBLK, NTHR, SMEM_SCAN>>>(out);
}

// round 17
// speedup vs baseline: 1.6232x; 1.0109x over previous
#include <cuda_runtime.h>
#include <cuda_fp16.h>
#include <cstdint>

#define N_DIM  2048
#define T_SEQ  8192
#define G_DIM  6144
#define SCANB  128     // scan blocks (persistent, all-resident)
#define WORKB  20      // gemm worker blocks
#define TOTB   (SCANB + WORKB)
#define NTHR   512
#define NWARP  16
#define PB     16      // output elements per scan block
#define NGATE  3
#define KFRAG  8
#define NTILE  ((T_SEQ / 128) * (G_DIM / 128))   // 64*48 = 3072
#define NB_N   (G_DIM / 128)                     // 48 tiles per m-block

// ---- scratch (device globals: allocation-free rule) ----
__device__ __half        g_x16[(size_t)T_SEQ * N_DIM];          // 32 MB
__device__ __half        g_WxT16[(size_t)G_DIM * N_DIM];        // 25 MB (transposed: [n][k])
__device__ float         g_gx[(size_t)T_SEQ * G_DIM];           // 192 MB
__device__ unsigned int  g_whpack[SCANB * NWARP * NGATE * KFRAG * 32 * 4]; // 25 MB packed A-frags
__device__ unsigned long long g_hpost[2][SCANB][8];             // 8B packets: {2×fp16, tag}
__device__ int           g_tilectr;                             // gemm work-stealing counter
__device__ int           g_gxready[T_SEQ / 128];                // per-m-block completion (==48 when ready)

// ---------------- fused prep: reset + conv_x + tiled WxT transpose + pack_wh ----------------
__global__ void prep(const float* __restrict__ x,
                     const float* __restrict__ Wx,
                     const float* __restrict__ Wh) {
    __shared__ __half tile[32][72];
    const size_t tg = blockIdx.x * (size_t)blockDim.x + threadIdx.x;
    const size_t nt = (size_t)gridDim.x * blockDim.x;
    const int    tl = threadIdx.x;

    // job 0: reset sync state
    if (tg == 0) g_tilectr = 0;
    for (size_t i = tg; i < T_SEQ / 128; i += nt) g_gxready[i] = 0;
    for (size_t i = tg; i < 2 * SCANB * 8; i += nt)
        ((unsigned long long*)g_hpost)[i] = 0ull;

    // job 1: x -> fp16
    {
        const float2* x2 = (const float2*)x;
        __half2* o = (__half2*)g_x16;
        const size_t n = (size_t)T_SEQ * N_DIM / 2;
        for (size_t i = tg; i < n; i += nt)
            o[i] = __float22half2_rn(x2[i]);
    }
    // job 3: Wh -> packed A-fragments
    {
        const size_t n = (size_t)SCANB * NWARP * NGATE * KFRAG * 32 * 4;
        for (size_t ii = tg; ii < n; ii += nt) {
            int idx  = (int)ii;
            int r    = idx & 3;
            int l    = (idx >> 2) & 31;
            int kf   = (idx >> 7) & 7;
            int rest = idx >> 10;
            int g    = rest % 3;
            int bw   = rest / 3;
            int w    = bw & 15;
            int b    = bw >> 4;
            int tid  = l & 3, gid = l >> 2;
            int j    = g * N_DIM + b * PB + gid + ((r & 1) ? 8 : 0);
            int k0   = w * 128 + kf * 16 + ((r & 2) ? 8 : 0) + 2 * tid;
            __half2 h;
            h.x = __float2half(Wh[(size_t)k0 * G_DIM + j]);
            h.y = __float2half(Wh[(size_t)(k0 + 1) * G_DIM + j]);
            g_whpack[idx] = *(unsigned int*)&h;
        }
    }
    // job 2: Wx -> WxT fp16 [n][k], tiled smem transpose
    {
        const int ntile = (N_DIM / 32) * (G_DIM / 64);
        for (int tix = blockIdx.x; tix < ntile; tix += gridDim.x) {
            int tk = tix & 63, tj = tix >> 6;
            int k0 = tk * 32, j0 = tj * 64;
            __syncthreads();
#pragma unroll
            for (int e = 0; e < 8; ++e) {
                int idx = tl + e * 256;
                int kk = idx >> 6, jj = idx & 63;
                tile[kk][jj] = __float2half(Wx[(size_t)(k0 + kk) * G_DIM + j0 + jj]);
            }
            __syncthreads();
#pragma unroll
            for (int e = 0; e < 8; ++e) {
                int idx = tl + e * 256;
                int jj = idx >> 5, kk = idx & 31;
                g_WxT16[(size_t)(j0 + jj) * N_DIM + k0 + kk] = tile[kk][jj];
            }
        }
    }
}

// ---------------- fused main kernel: 128 scan blocks + 20 gemm workers ----------------
#define CP_ASYNC16(sa, gp) \
    asm volatile("cp.async.ca.shared.global [%0], [%1], 16;" :: "r"(sa), "l"(gp))
#define CP_COMMIT() asm volatile("cp.async.commit_group;" ::: "memory")
#define GST 5120                    // halfs per stage per matrix (128*40)
#define FUSED_SMEM 40976            // 4*GST halfs *2B + jslot int, padded

__device__ __forceinline__ void gemm_worker(const float* __restrict__ bias,
                                            __half* gsm, int* jslot) {
    __half* Asm = gsm;
    __half* Bsm = gsm + 2 * GST;
    const int t = threadIdx.x, w = t >> 5, l = t & 31, tid = l & 3, gid = l >> 2;
    const int wm = w & 3, wn = w >> 2;
    const int row = t >> 2, c16 = (t & 3) * 8;

    for (;;) {
        if (t == 0) *jslot = atomicAdd(&g_tilectr, 1);
        __syncthreads();
        const int j = *jslot;
        if (j >= NTILE) break;
        const int mb = j / NB_N, nb = j - mb * NB_N;
        const int m0 = mb * 128, n0 = nb * 128;

        float acc[2][4][4];
#pragma unroll
        for (int mt = 0; mt < 2; ++mt)
#pragma unroll
            for (int nt = 0; nt < 4; ++nt)
#pragma unroll
                for (int q = 0; q < 4; ++q) acc[mt][nt][q] = 0.f;

        // stage 0
        {
            unsigned da = (unsigned)__cvta_generic_to_shared(Asm + row * 40 + c16);
            unsigned db = (unsigned)__cvta_generic_to_shared(Bsm + row * 40 + c16);
            CP_ASYNC16(da, g_x16   + (size_t)(m0 + row) * N_DIM + c16);
            CP_ASYNC16(db, g_WxT16 + (size_t)(n0 + row) * N_DIM + c16);
            CP_COMMIT();
        }
        const int NIT = N_DIM / 32;
        for (int i = 0; i < NIT; ++i) {
            const int s = i & 1;
            if (i + 1 < NIT) {
                const int kt = (i + 1) * 32;
                unsigned da = (unsigned)__cvta_generic_to_shared(Asm + (s ^ 1) * GST + row * 40 + c16);
                unsigned db = (unsigned)__cvta_generic_to_shared(Bsm + (s ^ 1) * GST + row * 40 + c16);
                CP_ASYNC16(da, g_x16   + (size_t)(m0 + row) * N_DIM + kt + c16);
                CP_ASYNC16(db, g_WxT16 + (size_t)(n0 + row) * N_DIM + kt + c16);
                CP_COMMIT();
                asm volatile("cp.async.wait_group 1;" ::: "memory");
            } else {
                asm volatile("cp.async.wait_group 0;" ::: "memory");
            }
            __syncthreads();
            const __half* As = Asm + s * GST;
            const __half* Bs = Bsm + s * GST;
#pragma unroll
            for (int sj = 0; sj < 2; ++sj) {
                const int ko = sj * 16;
                unsigned a[2][4];
#pragma unroll
                for (int mt = 0; mt < 2; ++mt) {
                    int rb = wm * 32 + mt * 16;
                    a[mt][0] = *(const unsigned*)(&As[(rb + gid)     * 40 + ko + 2 * tid]);
                    a[mt][1] = *(const unsigned*)(&As[(rb + gid + 8) * 40 + ko + 2 * tid]);
                    a[mt][2] = *(const unsigned*)(&As[(rb + gid)     * 40 + ko + 2 * tid + 8]);
                    a[mt][3] = *(const unsigned*)(&As[(rb + gid + 8) * 40 + ko + 2 * tid + 8]);
                }
#pragma unroll
                for (int nt = 0; nt < 4; ++nt) {
                    int cb = wn * 32 + nt * 8 + gid;
                    unsigned b0 = *(const unsigned*)(&Bs[cb * 40 + ko + 2 * tid]);
                    unsigned b1 = *(const unsigned*)(&Bs[cb * 40 + ko + 2 * tid + 8]);
#pragma unroll
                    for (int mt = 0; mt < 2; ++mt) {
                        asm volatile(
                            "mma.sync.aligned.m16n8k16.row.col.f32.f16.f16.f32 "
                            "{%0,%1,%2,%3},{%4,%5,%6,%7},{%8,%9},{%0,%1,%2,%3};"
                            : "+f"(acc[mt][nt][0]), "+f"(acc[mt][nt][1]),
                              "+f"(acc[mt][nt][2]), "+f"(acc[mt][nt][3])
                            : "r"(a[mt][0]), "r"(a[mt][1]), "r"(a[mt][2]), "r"(a[mt][3]),
                              "r"(b0), "r"(b1));
                    }
                }
            }
            __syncthreads();
        }
        // epilogue
#pragma unroll
        for (int mt = 0; mt < 2; ++mt)
#pragma unroll
            for (int nt = 0; nt < 4; ++nt) {
                int rw  = m0 + wm * 32 + mt * 16 + gid;
                int col = n0 + wn * 32 + nt * 8 + 2 * tid;
                float b0v = __ldg(bias + col), b1v = __ldg(bias + col + 1);
                g_gx[(size_t)rw * G_DIM + col]           = acc[mt][nt][0] + b0v;
                g_gx[(size_t)rw * G_DIM + col + 1]       = acc[mt][nt][1] + b1v;
                g_gx[(size_t)(rw + 8) * G_DIM + col]     = acc[mt][nt][2] + b0v;
                g_gx[(size_t)(rw + 8) * G_DIM + col + 1] = acc[mt][nt][3] + b1v;
            }
        __syncthreads();   // all STGs issued before publication
        if (t == 0) {
            asm volatile("fence.acq_rel.gpu;" ::: "memory");
            atomicAdd(&g_gxready[mb], 1);
        }
    }
}

__device__ __forceinline__ void scan_body(float* __restrict__ out, float* red) {
    const int b  = blockIdx.x;
    const int t0 = threadIdx.x;
    const int w  = t0 >> 5, l = t0 & 31, tid = l & 3, gid = l >> 2;
    const int i0 = b * PB;

    const unsigned* base = g_whpack + (size_t)b * 49152;
    unsigned breg[NGATE][KFRAG][4];
#pragma unroll
    for (int g = 0; g < NGATE; ++g)
#pragma unroll
        for (int kf = 0; kf < KFRAG; ++kf) {
            const uint4 v = *(const uint4*)(base + (size_t)(((w * NGATE + g) * KFRAG + kf) * 32 + l) * 4);
            breg[g][kf][0] = v.x; breg[g][kf][1] = v.y;
            breg[g][kf][2] = v.z; breg[g][kf][3] = v.w;
        }
    __syncthreads();

    const unsigned long long* src0 = &g_hpost[0][w * 8 + (l >> 3)][l & 7];
    const unsigned long long* src1 = &g_hpost[0][w * 8 + ((l + 32) >> 3)][(l + 32) & 7];
    const size_t bufstride = (size_t)SCANB * 8;

    float hprev = 0.f;
    int curmb = -1;   // warp 0: highest verified gx m-block

    for (int t = 0; t < T_SEQ; ++t) {
        float xa = 0.f, xb = 0.f;
        if (w == 0) {
            const int mb = t >> 7;
            if (mb != curmb) {
                if (l == 0) {
                    int v;
                    do {
                        asm volatile("ld.acquire.gpu.s32 %0, [%1];" : "=r"(v)
                                     : "l"(g_gxready + mb) : "memory");
                    } while (v < NB_N);
                }
                __syncwarp();
                curmb = mb;
            }
            const float* gxr = g_gx + (size_t)t * G_DIM + i0;
            if (l < 16) { xa = __ldg(gxr + l); xb = __ldg(gxr + 2 * N_DIM + l); }
            else        { xa = __ldg(gxr + N_DIM + l - 16); }
            // prefetch next step's gx only within the verified m-block
            if (l < 3 && t + 1 < T_SEQ && ((t + 1) >> 7) == curmb) {
                const float* p = g_gx + (size_t)(t + 1) * G_DIM + (size_t)l * N_DIM + i0;
                asm volatile("prefetch.global.L1 [%0];" :: "l"(p));
            }
        }

        unsigned p0, p1;
        {
            const unsigned long long* s0 = src0 + (t & 1) * bufstride;
            const unsigned long long* s1 = src1 + (t & 1) * bufstride;
            unsigned long long v;
            int got0 = 0, got1 = 0;
            do {
                if (!got0) {
                    asm volatile("ld.global.cg.b64 %0, [%1];" : "=l"(v) : "l"(s0) : "memory");
                    if ((unsigned)(v >> 32) == (unsigned)t) { p0 = (unsigned)v; got0 = 1; }
                }
                if (!got1) {
                    asm volatile("ld.global.cg.b64 %0, [%1];" : "=l"(v) : "l"(s1) : "memory");
                    if ((unsigned)(v >> 32) == (unsigned)t) { p1 = (unsigned)v; got1 = 1; }
                }
            } while (!(got0 & got1));
        }

        float acc[NGATE][4];
#pragma unroll
        for (int g = 0; g < NGATE; ++g)
#pragma unroll
            for (int q = 0; q < 4; ++q) acc[g][q] = 0.f;

#pragma unroll
        for (int kf = 0; kf < KFRAG; ++kf) {
            unsigned srcreg = (kf < 4) ? p0 : p1;
            unsigned b0 = __shfl_sync(0xffffffffu, srcreg, (kf * 8 + tid) & 31);
            unsigned b1 = __shfl_sync(0xffffffffu, srcreg, (kf * 8 + 4 + tid) & 31);
#pragma unroll
            for (int g = 0; g < NGATE; ++g) {
                asm volatile(
                    "mma.sync.aligned.m16n8k16.row.col.f32.f16.f16.f32 "
                    "{%0,%1,%2,%3},{%4,%5,%6,%7},{%8,%9},{%0,%1,%2,%3};"
                    : "+f"(acc[g][0]), "+f"(acc[g][1]), "+f"(acc[g][2]), "+f"(acc[g][3])
                    : "r"(breg[g][kf][0]), "r"(breg[g][kf][1]),
                      "r"(breg[g][kf][2]), "r"(breg[g][kf][3]),
                      "r"(b0), "r"(b1));
            }
        }
        float* redp = red + (t & 1) * 768;
        if (tid == 0) {
#pragma unroll
            for (int g = 0; g < NGATE; ++g) {
                redp[w * 48 + g * 16 + gid]     = acc[g][0];
                redp[w * 48 + g * 16 + gid + 8] = acc[g][2];
            }
        }
        __syncthreads();

        if (w == 0) {
            float sa = 0.f, sb = 0.f;
#pragma unroll
            for (int ww = 0; ww < NWARP; ++ww) {
                sa += redp[ww * 48 + l];
                sb += redp[ww * 48 + 32 + (l & 15)];
            }
            float sig = __fdividef(1.f, 1.f + __expf(-(xa + sa)));
            float r   = __shfl_sync(0xffffffffu, sig, (l + 16) & 31);
            float ci  = xb + r * sb;
            ci = fminf(fmaxf(ci, -15.f), 15.f);
            float e2  = __expf(2.f * ci);
            float cand = __fdividef(e2 - 1.f, e2 + 1.f);
            float hn = fmaf(sig, cand - hprev, hprev);
            if (l < 16) {
                hprev = hn;
                out[(size_t)t * N_DIM + i0 + l] = hn;
            }
            unsigned us = (unsigned)__half_as_ushort(__float2half(hn));
            unsigned lo = __shfl_sync(0xffffffffu, us, (2 * l) & 31);
            unsigned hi = __shfl_sync(0xffffffffu, us, (2 * l + 1) & 31);
            unsigned wreg = (hi << 16) | (lo & 0xffffu);
            if (l < 8) {
                unsigned long long pkt = (unsigned long long)wreg
                                       | ((unsigned long long)(unsigned)(t + 1) << 32);
                unsigned long long* dst = &g_hpost[(t + 1) & 1][b][l];
                asm volatile("st.global.cg.b64 [%0], %1;" :: "l"(dst), "l"(pkt) : "memory");
            }
        }
    }
}

__global__ void __launch_bounds__(NTHR, 1) gru_fused(float* __restrict__ out,
                                                     const float* __restrict__ bias) {
    extern __shared__ unsigned char smem[];
    if (blockIdx.x < SCANB) {
        scan_body(out, (float*)smem);
    } else {
        gemm_worker(bias, (__half*)smem, (int*)(smem + 4 * GST * 2));
    }
}

// ---------------- launcher ----------------
extern "C" void kernel_launch(void* const* d_in, const int* in_sizes, int n_in,
                              void* d_out, int out_size) {
    const float* x    = (const float*)d_in[0];
    const float* Wx   = (const float*)d_in[1];
    const float* Wh   = (const float*)d_in[2];
    const float* bias = (const float*)d_in[3];
    float* out = (float*)d_out;

    cudaFuncSetAttribute(gru_fused, cudaFuncAttributeMaxDynamicSharedMemorySize, FUSED_SMEM);

    prep<<<4096, 256>>>(x, Wx, Wh);
    gru_fused<<<TOTB, NTHR, FUSED_SMEM>>>(out, bias);
}